// round 8
// baseline (speedup 1.0000x reference)
#include <cuda_runtime.h>
#include <cstdint>

// Q8.8 SiLU via sigmoid LUT — exact all-float pipeline.
//   f   = x * 256                       (exact: *2^8)
//   qf  = rintf(f)                      (RNE == reference to_q88; clamp never fires for N(0,1))
//   idx = f2i_rn(clamp(f, -2048, 2048)) (== clamp(q,-2048,2048); +2048 folded into LDS address)
//   s'  = table[idx] / 256              (precomputed in shared, exact)
//   t   = qf * s'                       (EXACT: qf*s_q <= 32767*256 < 2^23, /256 is exp shift)
//   yf  = rintf(t)                      (RNE of exact value == reference sign-magnitude RNE>>8)
//   out = yf * (1/256)                  (exact)
//
// Table dtype probed at runtime (harness may widen int16). 32-bit words at
// word offsets 1024/1025 (bytes 4096..4103, in bounds for all layouts):
//   int32  : w0 = 5 (<0x10000), w1 != 0
//   int64  : w0 = lo = small,   w1 == 0
//   int16  : w0 = 0x00800080   (<0x01000000)
//   float32: w0 = 0x40A00000   (>=0x01000000)

#define THREADS 256
#define TABLE_N 4097

__device__ __forceinline__ void fill_lut(float* tab, const void* table) {
    const float inv256 = 1.0f / 256.0f;
    unsigned w0 = ((const unsigned*)table)[1024];
    unsigned w1 = ((const unsigned*)table)[1025];
    if (w0 < 0x10000u) {
        if (w1 == 0u) {                       // int64 entries
            const long long* t = (const long long*)table;
            for (int i = threadIdx.x; i < TABLE_N; i += THREADS)
                tab[i] = (float)(int)t[i] * inv256;
        } else {                              // int32 entries
            const int* t = (const int*)table;
            for (int i = threadIdx.x; i < TABLE_N; i += THREADS)
                tab[i] = (float)t[i] * inv256;
        }
    } else if (w0 < 0x01000000u) {            // int16 entries
        const short* t = (const short*)table;
        for (int i = threadIdx.x; i < TABLE_N; i += THREADS)
            tab[i] = (float)t[i] * inv256;
    } else {                                  // float32 entries (exact integers)
        const float* t = (const float*)table;
        for (int i = threadIdx.x; i < TABLE_N; i += THREADS)
            tab[i] = t[i] * inv256;
    }
}

__device__ __forceinline__ float silu_q88(float x, const float* __restrict__ tab) {
    float f  = x * 256.0f;                          // exact
    float qf = rintf(f);                            // RNE quantize (Q8.8 value, as float int)
    float fc = fminf(fmaxf(f, -2048.0f), 2048.0f);  // index clamp (memory safety)
    int idx  = __float2int_rn(fc);                  // [-2048, 2048]; +2048 folds into addr
    float t  = qf * tab[idx + 2048];                // exact product * 2^-8
    float yf = rintf(t);                            // RNE -> Q8.8 result (as float int)
    return yf * (1.0f / 256.0f);                    // exact dequant
}

__device__ __forceinline__ float4 silu4(float4 v, const float* __restrict__ tab) {
    float4 o;
    o.x = silu_q88(v.x, tab);
    o.y = silu_q88(v.y, tab);
    o.z = silu_q88(v.z, tab);
    o.w = silu_q88(v.w, tab);
    return o;
}

__global__ void __launch_bounds__(THREADS)
silu_lut_kernel(const float4* __restrict__ x,
                const void*   __restrict__ table,
                float4*       __restrict__ out,
                int n4)
{
    __shared__ float tab[TABLE_N];
    fill_lut(tab, table);
    __syncthreads();

    const int stride = gridDim.x * THREADS;
    int i = blockIdx.x * THREADS + threadIdx.x;

    // Main loop: 4 front-batched LDG.128 per thread (MLP=4) for latency hiding.
    for (; i + 3 * stride < n4; i += 4 * stride) {
        float4 v0 = x[i];
        float4 v1 = x[i + stride];
        float4 v2 = x[i + 2 * stride];
        float4 v3 = x[i + 3 * stride];
        out[i]              = silu4(v0, tab);
        out[i + stride]     = silu4(v1, tab);
        out[i + 2 * stride] = silu4(v2, tab);
        out[i + 3 * stride] = silu4(v3, tab);
    }
    for (; i < n4; i += stride)
        out[i] = silu4(x[i], tab);
}

// Tail handler (n not divisible by 4 — not expected here, but safe).
__global__ void __launch_bounds__(THREADS)
silu_lut_tail(const float* __restrict__ x,
              const void*  __restrict__ table,
              float*       __restrict__ out,
              int start, int n)
{
    __shared__ float tab[TABLE_N];
    fill_lut(tab, table);
    __syncthreads();

    int i = start + blockIdx.x * THREADS + threadIdx.x;
    if (i < n)
        out[i] = silu_q88(x[i], tab);
}

extern "C" void kernel_launch(void* const* d_in, const int* in_sizes, int n_in,
                              void* d_out, int out_size)
{
    // Table = whichever input has the small element count (4097); x = the other.
    int xi = 0, ti = 1;
    if (n_in >= 2 && in_sizes[1] > in_sizes[0]) { xi = 1; ti = 0; }

    const float* x     = (const float*)d_in[xi];
    const void*  table = d_in[ti];
    float*       out   = (float*)d_out;

    int n  = out_size;          // numel(x) == numel(out)
    int n4 = n >> 2;

    int blocks = 2368;
    int work_blocks = (n4 + THREADS - 1) / THREADS;
    if (work_blocks < blocks) blocks = work_blocks;
    if (blocks < 1) blocks = 1;

    if (n4 > 0)
        silu_lut_kernel<<<blocks, THREADS>>>((const float4*)x, table, (float4*)out, n4);

    int tail_start = n4 << 2;
    int tail = n - tail_start;
    if (tail > 0)
        silu_lut_tail<<<(tail + THREADS - 1) / THREADS, THREADS>>>(
            x, table, out, tail_start, n);
}

// round 9
// speedup vs baseline: 1.0269x; 1.0269x over previous
#include <cuda_runtime.h>
#include <cstdint>

// Q8.8 SiLU via sigmoid LUT — exact all-float pipeline (proof in R7):
//   f = x*256 (exact); qf = rintf(f) (RNE quantize);
//   idx = f2i_rn(clamp(f,±2048)); s' = table[idx]/256 (exact in shared);
//   t = qf*s' (EXACT: |qf*s_q| <= 32767*256 < 2^23); yf = rintf(t) (== RNE>>8);
//   out = yf/256 (exact).
//
// Table dtype probed at runtime (harness widens int16; probe words 1024/1025).

#define THREADS 256
#define TABLE_N 4097
#define UNROLL  8

__device__ __forceinline__ void fill_lut(float* tab, const void* table) {
    const float inv256 = 1.0f / 256.0f;
    unsigned w0 = ((const unsigned*)table)[1024];
    unsigned w1 = ((const unsigned*)table)[1025];
    if (w0 < 0x10000u) {
        if (w1 == 0u) {                       // int64 entries
            const long long* t = (const long long*)table;
            for (int i = threadIdx.x; i < TABLE_N; i += THREADS)
                tab[i] = (float)(int)t[i] * inv256;
        } else {                              // int32 entries
            const int* t = (const int*)table;
            for (int i = threadIdx.x; i < TABLE_N; i += THREADS)
                tab[i] = (float)t[i] * inv256;
        }
    } else if (w0 < 0x01000000u) {            // int16 entries
        const short* t = (const short*)table;
        for (int i = threadIdx.x; i < TABLE_N; i += THREADS)
            tab[i] = (float)t[i] * inv256;
    } else {                                  // float32 entries (exact integers)
        const float* t = (const float*)table;
        for (int i = threadIdx.x; i < TABLE_N; i += THREADS)
            tab[i] = t[i] * inv256;
    }
}

__device__ __forceinline__ float silu_q88(float x, const float* __restrict__ tab) {
    float f  = x * 256.0f;                          // exact
    float qf = rintf(f);                            // RNE quantize
    float fc = fminf(fmaxf(f, -2048.0f), 2048.0f);  // index clamp (memory safety)
    int idx  = __float2int_rn(fc);
    float t  = qf * tab[idx + 2048];                // exact
    float yf = rintf(t);                            // RNE
    return yf * (1.0f / 256.0f);                    // exact
}

__device__ __forceinline__ float4 silu4(float4 v, const float* __restrict__ tab) {
    float4 o;
    o.x = silu_q88(v.x, tab);
    o.y = silu_q88(v.y, tab);
    o.z = silu_q88(v.z, tab);
    o.w = silu_q88(v.w, tab);
    return o;
}

__global__ void __launch_bounds__(THREADS)
silu_lut_kernel(const float4* __restrict__ x,
                const void*   __restrict__ table,
                float4*       __restrict__ out,
                int n4)
{
    __shared__ float tab[TABLE_N];
    fill_lut(tab, table);
    __syncthreads();

    const int stride = gridDim.x * THREADS;
    int i = blockIdx.x * THREADS + threadIdx.x;

    // Main loop: 8 front-batched streaming LDG.128 per thread (MLP=8).
    for (; i + (UNROLL - 1) * stride < n4; i += UNROLL * stride) {
        float4 v[UNROLL];
#pragma unroll
        for (int u = 0; u < UNROLL; u++)
            v[u] = __ldcs(&x[i + u * stride]);
#pragma unroll
        for (int u = 0; u < UNROLL; u++)
            __stcs(&out[i + u * stride], silu4(v[u], tab));
    }
    // Remainder (empty for the bench shape; kept for generality).
    for (; i < n4; i += stride)
        __stcs(&out[i], silu4(__ldcs(&x[i]), tab));
}

// Tail handler (n not divisible by 4 — not expected here, but safe).
__global__ void __launch_bounds__(THREADS)
silu_lut_tail(const float* __restrict__ x,
              const void*  __restrict__ table,
              float*       __restrict__ out,
              int start, int n)
{
    __shared__ float tab[TABLE_N];
    fill_lut(tab, table);
    __syncthreads();

    int i = start + blockIdx.x * THREADS + threadIdx.x;
    if (i < n)
        out[i] = silu_q88(x[i], tab);
}

extern "C" void kernel_launch(void* const* d_in, const int* in_sizes, int n_in,
                              void* d_out, int out_size)
{
    // Table = whichever input has the small element count (4097); x = the other.
    int xi = 0, ti = 1;
    if (n_in >= 2 && in_sizes[1] > in_sizes[0]) { xi = 1; ti = 0; }

    const float* x     = (const float*)d_in[xi];
    const void*  table = d_in[ti];
    float*       out   = (float*)d_out;

    int n  = out_size;          // numel(x) == numel(out)
    int n4 = n >> 2;

    // Size the grid so the unrolled loop covers the data in whole iterations:
    // prefer an exact fit (n4 divisible by THREADS*UNROLL*iters), else ~2048.
    int blocks = 2048;
    {
        long long chunk = (long long)THREADS * UNROLL;
        long long full  = (n4 + chunk - 1) / chunk;   // blocks for 1 iter each
        // aim for ~2 iterations per thread
        long long b = (full + 1) / 2;
        if (b < 1) b = 1;
        if (b > 4096) b = 4096;
        blocks = (int)b;
    }

    if (n4 > 0)
        silu_lut_kernel<<<blocks, THREADS>>>((const float4*)x, table, (float4*)out, n4);

    int tail_start = n4 << 2;
    int tail = n - tail_start;
    if (tail > 0)
        silu_lut_tail<<<(tail + THREADS - 1) / THREADS, THREADS>>>(
            x, table, out, tail_start, n);
}

// round 10
// speedup vs baseline: 1.0868x; 1.0583x over previous
#include <cuda_runtime.h>
#include <cstdint>

// Q8.8 SiLU via sigmoid LUT — exact, ZERO conversion-pipe ops.
//
// Magic-number RNE (C = 1.5*2^23 = 12582912.0f):
//   g  = fmaf(x, 256, C)     : x*256 is exact; g in [2^23,2^24) (ulp=1), so the
//                              FFMA's RNE == round-half-to-even(x*256) + C. One op.
//   qf = g - C               : exact (Sterbenz), == reference to_q88 value.
//   bits(g) = 0x4B400000 + qf  -> idx = clamp(bits(g) - K, 0, 4096)  (pure ALU;
//                              == clamp(qf,-2048,2048)+2048, the reference index).
//   s' = table[idx]/256      : exact (power-of-2), precomputed in shared.
//   t  = qf*s'               : EXACT (|qf*s_q| <= 32767*256 < 2^23).
//   yf = fmaf(qf, s', C) - C : RNE of the exact t == reference RNE >> 8.
//   out = yf * (1/256)       : exact.
// => bit-identical to the reference for all |x*256| < 2^22 (bench max ~1.5e3).
//
// Table dtype probed at runtime (harness widens int16; probe words 1024/1025).

#define THREADS 256
#define TABLE_N 4097
#define UNROLL  4

#define MAGIC   12582912.0f            // 1.5 * 2^23
#define MAGIC_I 0x4B400000             // bits(MAGIC)
#define IDX_K   (MAGIC_I - 2048)       // bits(g) - IDX_K == qf + 2048

__device__ __forceinline__ void fill_lut(float* tab, const void* table) {
    const float inv256 = 1.0f / 256.0f;
    unsigned w0 = ((const unsigned*)table)[1024];
    unsigned w1 = ((const unsigned*)table)[1025];
    if (w0 < 0x10000u) {
        if (w1 == 0u) {                       // int64 entries
            const long long* t = (const long long*)table;
            for (int i = threadIdx.x; i < TABLE_N; i += THREADS)
                tab[i] = (float)(int)t[i] * inv256;
        } else {                              // int32 entries
            const int* t = (const int*)table;
            for (int i = threadIdx.x; i < TABLE_N; i += THREADS)
                tab[i] = (float)t[i] * inv256;
        }
    } else if (w0 < 0x01000000u) {            // int16 entries
        const short* t = (const short*)table;
        for (int i = threadIdx.x; i < TABLE_N; i += THREADS)
            tab[i] = (float)t[i] * inv256;
    } else {                                  // float32 entries (exact integers)
        const float* t = (const float*)table;
        for (int i = threadIdx.x; i < TABLE_N; i += THREADS)
            tab[i] = t[i] * inv256;
    }
}

__device__ __forceinline__ float silu_q88(float x, const float* __restrict__ tab) {
    float g  = fmaf(x, 256.0f, MAGIC);            // FFMA: RNE quantize folded in
    float qf = g - MAGIC;                          // exact Q8.8 value as float
    int   b  = __float_as_int(g) - IDX_K;          // qf + 2048 (pure integer)
    int  idx = min(max(b, 0), 4096);               // clamp (memory-safe LUT index)
    float h  = fmaf(qf, tab[idx], MAGIC);          // FFMA: RNE of exact product
    float yf = h - MAGIC;                          // exact
    return yf * (1.0f / 256.0f);                   // exact dequant
}

__device__ __forceinline__ float4 silu4(float4 v, const float* __restrict__ tab) {
    float4 o;
    o.x = silu_q88(v.x, tab);
    o.y = silu_q88(v.y, tab);
    o.z = silu_q88(v.z, tab);
    o.w = silu_q88(v.w, tab);
    return o;
}

__global__ void __launch_bounds__(THREADS)
silu_lut_kernel(const float4* __restrict__ x,
                const void*   __restrict__ table,
                float4*       __restrict__ out,
                int n4)
{
    __shared__ float tab[TABLE_N];
    fill_lut(tab, table);
    __syncthreads();

    const int stride = gridDim.x * THREADS;
    int i = blockIdx.x * THREADS + threadIdx.x;

    // Moderate MLP: 4 front-batched streaming LDG.128 per thread.
    for (; i + (UNROLL - 1) * stride < n4; i += UNROLL * stride) {
        float4 v[UNROLL];
#pragma unroll
        for (int u = 0; u < UNROLL; u++)
            v[u] = __ldcs(&x[i + u * stride]);
#pragma unroll
        for (int u = 0; u < UNROLL; u++)
            __stcs(&out[i + u * stride], silu4(v[u], tab));
    }
    for (; i < n4; i += stride)
        __stcs(&out[i], silu4(__ldcs(&x[i]), tab));
}

// Tail handler (n not divisible by 4 — not expected here, but safe).
__global__ void __launch_bounds__(THREADS)
silu_lut_tail(const float* __restrict__ x,
              const void*  __restrict__ table,
              float*       __restrict__ out,
              int start, int n)
{
    __shared__ float tab[TABLE_N];
    fill_lut(tab, table);
    __syncthreads();

    int i = start + blockIdx.x * THREADS + threadIdx.x;
    if (i < n)
        out[i] = silu_q88(x[i], tab);
}

extern "C" void kernel_launch(void* const* d_in, const int* in_sizes, int n_in,
                              void* d_out, int out_size)
{
    // Table = whichever input has the small element count (4097); x = the other.
    int xi = 0, ti = 1;
    if (n_in >= 2 && in_sizes[1] > in_sizes[0]) { xi = 1; ti = 0; }

    const float* x     = (const float*)d_in[xi];
    const void*  table = d_in[ti];
    float*       out   = (float*)d_out;

    int n  = out_size;          // numel(x) == numel(out)
    int n4 = n >> 2;

    // ~2048 blocks: 4-iteration grid-stride on the bench shape, modest
    // redundant table traffic from per-block LUT fills.
    int blocks = 2048;
    int work_blocks = (n4 + THREADS - 1) / THREADS;
    if (work_blocks < blocks) blocks = work_blocks;
    if (blocks < 1) blocks = 1;

    if (n4 > 0)
        silu_lut_kernel<<<blocks, THREADS>>>((const float4*)x, table, (float4*)out, n4);

    int tail_start = n4 << 2;
    int tail = n - tail_start;
    if (tail > 0)
        silu_lut_tail<<<(tail + THREADS - 1) / THREADS, THREADS>>>(
            x, table, out, tail_start, n);
}

// round 11
// speedup vs baseline: 1.1310x; 1.0406x over previous
#include <cuda_runtime.h>
#include <cstdint>

// Q8.8 SiLU via sigmoid LUT — exact magic-number pipeline + BANK-PRIVATE u8 LUT.
//
// Math (all steps exact / RNE-equivalent to the reference, proofs R7/R9):
//   g  = fmaf(x,256,MAGIC); qf = g-MAGIC  == RNE(x*256) (Q8.8 quantize)
//   idx = clamp(bits(g)-IDX_K, 0, 4096)   == clamp(x_q,-2048,2048)+2048
//   s   = (idx>=thr) ? 256 : u8tab[idx]   (u8tab = min(s_q,255); thr = start of
//                                          the contiguous s_q==256 plateau)
//   p  = qf * (float)s                    (exact: |qf*s| <= 32767*256 < 2^23)
//   yf = fmaf(p, 1/256, MAGIC) - MAGIC    == RNE(x_q*s_q >> 8)  (Q16.16->Q8.8)
//   out = yf * (1/256)                    (exact dequant)
//
// LUT layout: one private copy per bank. Entry i for lane l at byte
//   (i>>2)*128 + l*4 + (i&3)   -> lane l only touches bank l
// => every LDS.U8 is 1 wavefront (zero conflicts) for ANY index distribution.
// Size: 1024 words/copy * 32 copies * 4B = 131072 B dynamic shared.
//
// Table dtype probed at runtime (harness widens int16; probe words 1024/1025).

#define THREADS   1024
#define TABLE_N   4097
#define UNROLL    4
#define LUT_BYTES 131072

#define MAGIC   12582912.0f            // 1.5 * 2^23
#define MAGIC_I 0x4B400000             // bits(MAGIC)
#define IDX_K   (MAGIC_I - 2048)       // bits(g) - IDX_K == qf + 2048

// ---- generalized table accessor (dtype probed once per block) ----
__device__ __forceinline__ int probe_mode(const void* table) {
    unsigned w0 = ((const unsigned*)table)[1024];
    unsigned w1 = ((const unsigned*)table)[1025];
    if (w0 < 0x10000u)      return (w1 == 0u) ? 0 : 1;   // 0=int64, 1=int32
    if (w0 < 0x01000000u)   return 2;                    // int16
    return 3;                                            // float32
}
__device__ __forceinline__ int tab_entry(const void* table, int i, int mode) {
    switch (mode) {
        case 0:  return (int)((const long long*)table)[i];
        case 1:  return ((const int*)table)[i];
        case 2:  return (int)((const short*)table)[i];
        default: return __float2int_rn(((const float*)table)[i]);
    }
}

__global__ void __launch_bounds__(THREADS)
silu_lut_kernel(const float4* __restrict__ x,
                const void*   __restrict__ table,
                float4*       __restrict__ out,
                int n4)
{
    extern __shared__ unsigned char lut[];   // 128 KB, bank-private copies
    __shared__ int thr_s;

    const int tid  = threadIdx.x;
    const int mode = probe_mode(table);
    if (tid == 0) thr_s = 1 << 30;
    __syncthreads();

    // ---- fill: thread tid packs entries 4*tid..4*tid+3, writes 32 copies ----
    {
        int i0 = tid * 4;                      // tid < 1024 -> covers 0..4095
        unsigned b0 = (unsigned)min(tab_entry(table, i0 + 0, mode), 255);
        unsigned b1 = (unsigned)min(tab_entry(table, i0 + 1, mode), 255);
        unsigned b2 = (unsigned)min(tab_entry(table, i0 + 2, mode), 255);
        unsigned b3 = (unsigned)min(tab_entry(table, i0 + 3, mode), 255);
        unsigned val = b0 | (b1 << 8) | (b2 << 16) | (b3 << 24);
        unsigned* row = (unsigned*)(lut + tid * 128);
#pragma unroll
        for (int l = 0; l < 32; l++) {
            int bank = (l + tid) & 31;         // rotate to avoid write conflicts
            row[bank] = val;
        }
        // find start of the s_q == 256 plateau (sigmoid monotone => contiguous)
        for (int i = tid + 1; i <= 4096; i += THREADS) {
            if (tab_entry(table, i, mode) == 256 &&
                tab_entry(table, i - 1, mode) != 256)
                atomicMin(&thr_s, i);
        }
    }
    __syncthreads();

    const int   thr   = thr_s;
    const int   lane4 = (tid & 31) << 2;       // this lane's bank offset
    const unsigned char* mylut = lut + lane4;

    const int stride = gridDim.x * THREADS;
    int i = blockIdx.x * THREADS + tid;

    for (; i + (UNROLL - 1) * stride < n4; i += UNROLL * stride) {
        float4 v[UNROLL];
#pragma unroll
        for (int u = 0; u < UNROLL; u++)
            v[u] = __ldcs(&x[i + u * stride]);
#pragma unroll
        for (int u = 0; u < UNROLL; u++) {
            float4 o;
            float* vi = (float*)&v[u];
            float* oi = (float*)&o;
#pragma unroll
            for (int e = 0; e < 4; e++) {
                float g  = fmaf(vi[e], 256.0f, MAGIC);
                float qf = g - MAGIC;
                int   b  = __float_as_int(g) - IDX_K;
                int  idx = min(max(b, 0), 4096);
                int idxm = min(idx, 4095);
                int    s = (int)mylut[((idxm >> 2) << 7) + (idxm & 3)];
                s = (idx >= thr) ? 256 : s;
                float p  = qf * (float)s;                    // exact
                float yf = fmaf(p, 1.0f / 256.0f, MAGIC) - MAGIC;  // RNE
                oi[e] = yf * (1.0f / 256.0f);
            }
            __stcs(&out[i + u * stride], o);
        }
    }
    for (; i < n4; i += stride) {
        float4 v = __ldcs(&x[i]);
        float4 o;
        float* vi = (float*)&v;
        float* oi = (float*)&o;
#pragma unroll
        for (int e = 0; e < 4; e++) {
            float g  = fmaf(vi[e], 256.0f, MAGIC);
            float qf = g - MAGIC;
            int   b  = __float_as_int(g) - IDX_K;
            int  idx = min(max(b, 0), 4096);
            int idxm = min(idx, 4095);
            int    s = (int)mylut[((idxm >> 2) << 7) + (idxm & 3)];
            s = (idx >= thr) ? 256 : s;
            float p  = qf * (float)s;
            float yf = fmaf(p, 1.0f / 256.0f, MAGIC) - MAGIC;
            oi[e] = yf * (1.0f / 256.0f);
        }
        __stcs(&out[i], o);
    }
}

// Tail (n not divisible by 4 — never runs on the bench shape). Direct global
// table access; integer-exact path.
__global__ void silu_lut_tail(const float* __restrict__ x,
                              const void*  __restrict__ table,
                              float*       __restrict__ out,
                              int start, int n)
{
    int mode = probe_mode(table);
    int i = start + blockIdx.x * blockDim.x + threadIdx.x;
    if (i < n) {
        float g  = fmaf(x[i], 256.0f, MAGIC);
        float qf = g - MAGIC;
        int   b  = __float_as_int(g) - IDX_K;
        int  idx = min(max(b, 0), 4096);
        int    s = tab_entry(table, idx, mode);
        float p  = qf * (float)s;
        float yf = fmaf(p, 1.0f / 256.0f, MAGIC) - MAGIC;
        out[i] = yf * (1.0f / 256.0f);
    }
}

extern "C" void kernel_launch(void* const* d_in, const int* in_sizes, int n_in,
                              void* d_out, int out_size)
{
    // Table = whichever input has the small element count (4097); x = the other.
    int xi = 0, ti = 1;
    if (n_in >= 2 && in_sizes[1] > in_sizes[0]) { xi = 1; ti = 0; }

    const float* x     = (const float*)d_in[xi];
    const void*  table = d_in[ti];
    float*       out   = (float*)d_out;

    int n  = out_size;          // numel(x) == numel(out)
    int n4 = n >> 2;

    cudaFuncSetAttribute(silu_lut_kernel,
                         cudaFuncAttributeMaxDynamicSharedMemorySize, LUT_BYTES);

    // One block per SM (128 KB smem/block); grid-stride covers the rest.
    int blocks = 148;
    int work_blocks = (n4 + THREADS - 1) / THREADS;
    if (work_blocks < blocks) blocks = work_blocks;
    if (blocks < 1) blocks = 1;

    if (n4 > 0)
        silu_lut_kernel<<<blocks, THREADS, LUT_BYTES>>>(
            (const float4*)x, table, (float4*)out, n4);

    int tail_start = n4 << 2;
    int tail = n - tail_start;
    if (tail > 0)
        silu_lut_tail<<<(tail + 255) / 256, 256>>>(x, table, out, tail_start, n);
}